// round 12
// baseline (speedup 1.0000x reference)
#include <cuda_runtime.h>
#include <math.h>

typedef unsigned long long ull;

// ---------------------------------------------------------------------------
// packed fp32x2 helpers (Blackwell FFMA2)
// ---------------------------------------------------------------------------
#define FMA2(d, a, b, c) \
    asm("fma.rn.f32x2 %0, %1, %2, %3;" : "=l"(d) : "l"(a), "l"(b), "l"(c))

static __device__ __forceinline__ ull pack2(float lo, float hi) {
    ull r; asm("mov.b64 %0, {%1, %2};" : "=l"(r) : "f"(lo), "f"(hi)); return r;
}
static __device__ __forceinline__ float2 unpack2(ull v) {
    float2 r; asm("mov.b64 {%0, %1}, %2;" : "=f"(r.x), "=f"(r.y) : "l"(v)); return r;
}
static __device__ __forceinline__ ull lds64(const float* p) {
    return *reinterpret_cast<const ull*>(p);
}

// Scratch: per-image softmax probabilities (1024 batches * 16 digits * 10)
__device__ float g_probs[1024 * 16 * 10];

// ---------------------------------------------------------------------------
// shared memory layout (float offsets)
// ---------------------------------------------------------------------------
#define OFF_DW1T  0        // [120][260]  transposed dw1, 16B-aligned rows
#define DW1_STR   260
#define OFF_DW2T  31200    // [84][124]   transposed dw2, 16B-aligned rows
#define DW2_STR   124
#define OFF_W1P   41616    // [25][8]  conv1 weights, 6 ch + 2 pad per tap
#define OFF_W2X   41816    // 2400 interleaved conv2 weights
#define OFF_B1    44216    // 8
#define OFF_B2    44224    // 16
#define OFF_DB1   44240    // 120
#define OFF_DB2   44360    // 88
#define OFF_DB3   44448    // 16
#define OFF_IMG   44464    // [4][784]
#define OFF_P1T   47600    // [4][6][12][24]  pooled conv1, dup pairs
#define P1_IMG_STR 1728
#define OFF_P2    54512    // [4][264]
#define P2_STR    264
#define OFF_FC1   55568    // [4][120]
#define OFF_FC2   56048    // [4][88]
#define OFF_LOG   56400    // [4][12]
#define OFF_XCH   56448    // [2][512]  conv2 dy-exchange scratch
#define SMEM_FLOATS 57472  // = 229,888 bytes

// barriers: ids 1/2 = full half (256), ids 5/6 = fc group (96)
#define HBAR(h) asm volatile("bar.sync %0, 256;" :: "r"((h) + 1) : "memory")
#define FBAR(h) asm volatile("bar.sync %0, 96;"  :: "r"((h) + 5) : "memory")

// ---------------------------------------------------------------------------
// conv1 (5x5->6) + relu + pool for a PAIR of images. t<144 active.
// ---------------------------------------------------------------------------
__device__ __noinline__ void do_conv1_pair(float* sm, int t, int slot0)
{
    if (t >= 144) return;
    const int im  = t / 72;
    const int r72 = t % 72;
    const int py = r72 / 6, xg = r72 % 6, x0 = 4 * xg;
    const float* ibase = sm + OFF_IMG + (slot0 + im) * 784 + 2 * py * 28 + x0;
    float* s_p1 = sm + OFF_P1T + (slot0 + im) * P1_IMG_STR;

    ull bp[3];
    #pragma unroll
    for (int cp = 0; cp < 3; cp++)
        bp[cp] = pack2(sm[OFF_B1 + 2 * cp], sm[OFF_B1 + 2 * cp + 1]);
    ull acc[2][4][3];
    #pragma unroll
    for (int dy = 0; dy < 2; dy++)
        #pragma unroll
        for (int dx = 0; dx < 4; dx++)
            #pragma unroll
            for (int cp = 0; cp < 3; cp++) acc[dy][dx][cp] = bp[cp];

    #pragma unroll
    for (int r = 0; r < 6; r++) {
        float4 v0 = *reinterpret_cast<const float4*>(ibase + r * 28);
        float4 v1 = *reinterpret_cast<const float4*>(ibase + r * 28 + 4);
        ull ap[8];
        ap[0] = pack2(v0.x, v0.x); ap[1] = pack2(v0.y, v0.y);
        ap[2] = pack2(v0.z, v0.z); ap[3] = pack2(v0.w, v0.w);
        ap[4] = pack2(v1.x, v1.x); ap[5] = pack2(v1.y, v1.y);
        ap[6] = pack2(v1.z, v1.z); ap[7] = pack2(v1.w, v1.w);
        #pragma unroll
        for (int dy = 0; dy < 2; dy++) {
            const int ky = r - dy;
            if (ky < 0 || ky > 4) continue;
            #pragma unroll
            for (int kx = 0; kx < 5; kx++) {
                const float* wp = sm + OFF_W1P + (ky * 5 + kx) * 8;
                ulonglong2 w01 = *reinterpret_cast<const ulonglong2*>(wp);
                ull w2 = lds64(wp + 4);
                #pragma unroll
                for (int dx = 0; dx < 4; dx++) {
                    FMA2(acc[dy][dx][0], ap[kx + dx], w01.x, acc[dy][dx][0]);
                    FMA2(acc[dy][dx][1], ap[kx + dx], w01.y, acc[dy][dx][1]);
                    FMA2(acc[dy][dx][2], ap[kx + dx], w2,    acc[dy][dx][2]);
                }
            }
        }
    }
    #pragma unroll
    for (int cp = 0; cp < 3; cp++) {
        #pragma unroll
        for (int dxp = 0; dxp < 2; dxp++) {
            float2 a0 = unpack2(acc[0][2 * dxp][cp]);
            float2 a1 = unpack2(acc[0][2 * dxp + 1][cp]);
            float2 b0 = unpack2(acc[1][2 * dxp][cp]);
            float2 b1 = unpack2(acc[1][2 * dxp + 1][cp]);
            float m0 = fmaxf(fmaxf(fmaxf(a0.x, a1.x), fmaxf(b0.x, b1.x)), 0.0f);
            float m1 = fmaxf(fmaxf(fmaxf(a0.y, a1.y), fmaxf(b0.y, b1.y)), 0.0f);
            const int px = 2 * xg + dxp;
            *reinterpret_cast<ull*>(s_p1 + ((2 * cp)     * 12 + py) * 24 + 2 * px) = pack2(m0, m0);
            *reinterpret_cast<ull*>(s_p1 + ((2 * cp + 1) * 12 + py) * 24 + 2 * px) = pack2(m1, m1);
        }
    }
}

// ---------------------------------------------------------------------------
// conv2 dy-half: thread t (0..255) computes ONE conv row (dy = t>>7) of unit
// u = t&127 -> (im, py, xg, cg). acc[dx] = 4 conv cols, 2 channels packed.
// ---------------------------------------------------------------------------
static __device__ __forceinline__ void conv2_half_compute(
    const float* sm, int t, int slot0, ull acc[4])
{
    const int dy = t >> 7;
    const int u  = t & 127;
    const int im = u >> 6;
    const int v  = u & 63;
    const int py = v >> 4, xg = (v >> 3) & 1, cg = v & 7;
    const int x0 = 4 * xg;
    const float* pbase = sm + OFF_P1T + (slot0 + im) * P1_IMG_STR;
    const float* wbase = sm + OFF_W2X + cg * 4;

    ull bp = lds64(sm + OFF_B2 + 2 * cg);
    acc[0] = bp; acc[1] = bp; acc[2] = bp; acc[3] = bp;

    const int yc = 2 * py + dy;
    #pragma unroll
    for (int ky = 0; ky < 5; ky++) {
        const int iy = yc + ky;
        #pragma unroll
        for (int ip = 0; ip < 3; ip++) {
            const float* r0 = pbase + ((2 * ip) * 12 + iy) * 24 + 2 * x0;
            const float* r1 = r0 + 288;
            ull ap0[8], ap1[8];
            #pragma unroll
            for (int jj = 0; jj < 4; jj++) {
                ulonglong2 t0 = *reinterpret_cast<const ulonglong2*>(r0 + 4 * jj);
                ap0[2 * jj] = t0.x; ap0[2 * jj + 1] = t0.y;
                ulonglong2 t1 = *reinterpret_cast<const ulonglong2*>(r1 + 4 * jj);
                ap1[2 * jj] = t1.x; ap1[2 * jj + 1] = t1.y;
            }
            #pragma unroll
            for (int kx = 0; kx < 5; kx++) {
                ulonglong2 w = *reinterpret_cast<const ulonglong2*>(
                    wbase + ((ky * 5 + kx) * 3 + ip) * 32);
                #pragma unroll
                for (int dx = 0; dx < 4; dx++) {
                    FMA2(acc[dx], ap0[kx + dx], w.x, acc[dx]);
                    FMA2(acc[dx], ap1[kx + dx], w.y, acc[dx]);
                }
            }
        }
    }
}

// ---------------------------------------------------------------------------
// fc chain on 96 threads (tF = 0..95).
// ---------------------------------------------------------------------------
static __device__ __forceinline__ void do_fc1_96(float* sm, int tF, int slot0)
{
    for (int u = tF; u < 240; u += 96) {
        const int j = u >> 1, im = u & 1;
        const float* act = sm + OFF_P2 + (slot0 + im) * P2_STR;
        const float* wr  = sm + OFF_DW1T + j * DW1_STR;
        ull acc0 = pack2(0.0f, 0.0f), acc1 = pack2(0.0f, 0.0f);
        #pragma unroll 8
        for (int k = 0; k < 256; k += 4) {
            ulonglong2 av = *reinterpret_cast<const ulonglong2*>(act + k);
            ulonglong2 wv = *reinterpret_cast<const ulonglong2*>(wr + k);
            FMA2(acc0, av.x, wv.x, acc0);
            FMA2(acc1, av.y, wv.y, acc1);
        }
        float2 s0 = unpack2(acc0), s1 = unpack2(acc1);
        float v = s0.x + s0.y + s1.x + s1.y + sm[OFF_DB1 + j];
        sm[OFF_FC1 + (slot0 + im) * 120 + j] = fmaxf(v, 0.0f);
    }
}

static __device__ __forceinline__ void do_fc2_96(float* sm, int tF, int slot0)
{
    for (int u = tF; u < 168; u += 96) {
        const int j = u >> 1, im = u & 1;
        const float* act = sm + OFF_FC1 + (slot0 + im) * 120;
        const float* wr  = sm + OFF_DW2T + j * DW2_STR;
        ull acc0 = pack2(0.0f, 0.0f), acc1 = pack2(0.0f, 0.0f);
        #pragma unroll 6
        for (int k = 0; k < 120; k += 4) {
            ulonglong2 av = *reinterpret_cast<const ulonglong2*>(act + k);
            ulonglong2 wv = *reinterpret_cast<const ulonglong2*>(wr + k);
            FMA2(acc0, av.x, wv.x, acc0);
            FMA2(acc1, av.y, wv.y, acc1);
        }
        float2 s0 = unpack2(acc0), s1 = unpack2(acc1);
        float v = s0.x + s0.y + s1.x + s1.y + sm[OFF_DB2 + j];
        sm[OFF_FC2 + (slot0 + im) * 88 + j] = fmaxf(v, 0.0f);
    }
}

// fc3 (dw3 from global via __ldg) + softmax, inside one warp (tF 0..31).
static __device__ __forceinline__ void do_fc3_softmax_96(
    float* sm, const float* __restrict__ dw3, int tF, int slot0, int img0, int nimg)
{
    if (tF >= 32) return;
    if (tF < 20) {
        const int j = tF >> 1, im = tF & 1;
        const float* act = sm + OFF_FC2 + (slot0 + im) * 88;
        float acc = sm[OFF_DB3 + j];
        #pragma unroll 4
        for (int k = 0; k < 84; k++)
            acc = fmaf(act[k], __ldg(&dw3[k * 10 + j]), acc);
        sm[OFF_LOG + (slot0 + im) * 12 + j] = acc;
    }
    __syncwarp();
    if (tF < 2) {
        const int img = img0 + tF;
        if (img < nimg) {
            const float* lg = sm + OFF_LOG + (slot0 + tF) * 12;
            float mx = lg[0];
            #pragma unroll
            for (int j = 1; j < 10; j++) mx = fmaxf(mx, lg[j]);
            float e[10], s = 0.0f;
            #pragma unroll
            for (int j = 0; j < 10; j++) { e[j] = __expf(lg[j] - mx); s += e[j]; }
            float inv = 1.0f / s;
            float* po = g_probs + (size_t)img * 10;
            #pragma unroll
            for (int j = 0; j < 10; j++) po[j] = e[j] * inv;
        }
    }
}

static __device__ __forceinline__ void do_prefetch(float* sm, int t, int slot0,
                                                   const float* inputs,
                                                   int nb, int nimg)
{
    // threads t in [128,256): copy this half's next 2 images
    const int i0 = t - 128;
    if (nb + slot0 < nimg) {
        const float4* iv = reinterpret_cast<const float4*>(inputs + (size_t)(nb + slot0) * 784);
        float4* ov = reinterpret_cast<float4*>(sm + OFF_IMG + slot0 * 784);
        for (int i = i0; i < 196; i += 128) ov[i] = iv[i];
    }
    if (nb + slot0 + 1 < nimg) {
        const float4* iv = reinterpret_cast<const float4*>(inputs + (size_t)(nb + slot0 + 1) * 784);
        float4* ov = reinterpret_cast<float4*>(sm + OFF_IMG + (slot0 + 1) * 784);
        for (int i = i0; i < 196; i += 128) ov[i] = iv[i];
    }
}

// ---------------------------------------------------------------------------
// Kernel 1: persistent fused LeNet. 148 CTAs x 512 threads; two independent
// 256-thread halves, each a software pipeline over pairs of images:
//   P1a: conv2 dy-halves on ALL 8 warps (dy1 -> XCH)
//   P1b: dy0 pool+store P2  ||  dy1 prefetch(next pair)
//   P2 : conv1(next pair) [warps 0-4]  ||  fc chain(cur) [warps 5-7]
// ---------------------------------------------------------------------------
__global__ void __launch_bounds__(512, 1) cnn_kernel(
    const float* __restrict__ inputs,
    const float* __restrict__ cw1, const float* __restrict__ cb1,
    const float* __restrict__ cw2, const float* __restrict__ cb2,
    const float* __restrict__ dw1, const float* __restrict__ db1,
    const float* __restrict__ dw2, const float* __restrict__ db2,
    const float* __restrict__ dw3, const float* __restrict__ db3,
    int nimg)
{
    extern __shared__ float sm[];
    const int tid = threadIdx.x;

    // ---- one-time weight staging ----
    for (int idx = tid; idx < 256 * 120; idx += 512) {
        int k = idx / 120, j = idx % 120;
        sm[OFF_DW1T + j * DW1_STR + k] = dw1[idx];
    }
    for (int idx = tid; idx < 120 * 84; idx += 512) {
        int k = idx / 84, j = idx % 84;
        sm[OFF_DW2T + j * DW2_STR + k] = dw2[idx];
    }
    for (int idx = tid; idx < 150; idx += 512) {
        int pk = idx / 6, c = idx % 6;
        sm[OFF_W1P + pk * 8 + c] = cw1[idx];
    }
    for (int idx = tid; idx < 2400; idx += 512) {
        int p = idx >> 4, ch = idx & 15;
        int pk = p / 6, i = p % 6;
        sm[OFF_W2X + (pk * 3 + (i >> 1)) * 32 + (ch >> 1) * 4 + (i & 1) * 2 + (ch & 1)]
            = cw2[idx];
    }
    if (tid < 6)   sm[OFF_B1  + tid] = cb1[tid];
    if (tid < 16)  sm[OFF_B2  + tid] = cb2[tid];
    if (tid < 120) sm[OFF_DB1 + tid] = db1[tid];
    if (tid < 84)  sm[OFF_DB2 + tid] = db2[tid];
    if (tid < 10)  sm[OFF_DB3 + tid] = db3[tid];

    // ---- prologue: load first batch of 4 images (guarded per image) ----
    {
        const int b0 = blockIdx.x * 4;
        #pragma unroll
        for (int k = 0; k < 4; k++) {
            if (b0 + k < nimg) {
                const float4* iv = reinterpret_cast<const float4*>(inputs + (size_t)(b0 + k) * 784);
                float4* ov = reinterpret_cast<float4*>(sm + OFF_IMG + k * 784);
                for (int i = tid; i < 196; i += 512) ov[i] = iv[i];
            }
        }
    }
    __syncthreads();

    const int h     = tid >> 8;      // half 0/1
    const int t     = tid & 255;     // thread within half
    const int slot0 = h * 2;
    const int qstep = gridDim.x * 4;
    float* xch = sm + OFF_XCH + h * 512;

    // ---- pipeline prologue: conv1 on the first pair ----
    do_conv1_pair(sm, t, slot0);
    HBAR(h);

    for (int base = blockIdx.x * 4; base < nimg; base += qstep) {
        // ---- P1a: conv2 dy-halves on all 256 threads ----
        ull c2[4];
        conv2_half_compute(sm, t, slot0, c2);
        if (t >= 128) {
            // dy1: pre-reduce column pairs, hand off to partner
            float2 a0 = unpack2(c2[0]), a1 = unpack2(c2[1]);
            float2 a2 = unpack2(c2[2]), a3 = unpack2(c2[3]);
            float4 v;
            v.x = fmaxf(a0.x, a1.x); v.y = fmaxf(a0.y, a1.y);
            v.z = fmaxf(a2.x, a3.x); v.w = fmaxf(a2.y, a3.y);
            *reinterpret_cast<float4*>(xch + (t - 128) * 4) = v;
        }
        HBAR(h);

        // ---- P1b: dy0 pool+store, dy1 prefetch ----
        if (t < 128) {
            float2 a0 = unpack2(c2[0]), a1 = unpack2(c2[1]);
            float2 a2 = unpack2(c2[2]), a3 = unpack2(c2[3]);
            float4 p = *reinterpret_cast<const float4*>(xch + t * 4);
            float m0lo = fmaxf(fmaxf(fmaxf(a0.x, a1.x), p.x), 0.0f);
            float m0hi = fmaxf(fmaxf(fmaxf(a0.y, a1.y), p.y), 0.0f);
            float m1lo = fmaxf(fmaxf(fmaxf(a2.x, a3.x), p.z), 0.0f);
            float m1hi = fmaxf(fmaxf(fmaxf(a2.y, a3.y), p.w), 0.0f);
            const int im = t >> 6;
            const int v  = t & 63;
            const int py = v >> 4, xg = (v >> 3) & 1, cg = v & 7;
            float* s_p2 = sm + OFF_P2 + (slot0 + im) * P2_STR;
            *reinterpret_cast<ull*>(s_p2 + (py * 4 + 2 * xg)     * 16 + 2 * cg) = pack2(m0lo, m0hi);
            *reinterpret_cast<ull*>(s_p2 + (py * 4 + 2 * xg + 1) * 16 + 2 * cg) = pack2(m1lo, m1hi);
        } else {
            do_prefetch(sm, t, slot0, inputs, base + qstep, nimg);
        }
        HBAR(h);

        // ---- P2: conv1(next pair) || fc chain(cur pair) ----
        if (t < 160) {
            do_conv1_pair(sm, t, slot0);     // harmless on stale data past end
        } else {
            const int tF = t - 160;
            do_fc1_96(sm, tF, slot0);
            FBAR(h);
            do_fc2_96(sm, tF, slot0);
            FBAR(h);
            do_fc3_softmax_96(sm, dw3, tF, slot0, base + slot0, nimg);
        }
        HBAR(h);
    }
}

// ---------------------------------------------------------------------------
// Kernel 2: Luhn DP (register-resident, high-MLP loads).
// ---------------------------------------------------------------------------
template <int N>
__device__ __forceinline__ float luhn_eval(const float* __restrict__ p)
{
    const int LUHN[10] = {0, 5, 1, 6, 2, 7, 3, 8, 4, 9};
    float4 v[(N * 10) / 4];
    const float4* pv = reinterpret_cast<const float4*>(p);
    #pragma unroll
    for (int i = 0; i < (N * 10) / 4; i++) v[i] = pv[i];
    float d[N * 10];
    #pragma unroll
    for (int i = 0; i < (N * 10) / 4; i++) {
        d[4 * i] = v[i].x; d[4 * i + 1] = v[i].y;
        d[4 * i + 2] = v[i].z; d[4 * i + 3] = v[i].w;
    }
    const int m = N - 1;
    float cur[10];
    #pragma unroll
    for (int j = 0; j < 10; j++)
        cur[j] = ((0 % 2) == (m % 2)) ? d[10 + LUHN[j]] : d[10 + j];
    #pragma unroll
    for (int i = 1; i < m; i++) {
        float dd[10];
        #pragma unroll
        for (int j = 0; j < 10; j++)
            dd[j] = ((i % 2) == (m % 2)) ? d[(i + 1) * 10 + LUHN[j]] : d[(i + 1) * 10 + j];
        float nxt[10];
        #pragma unroll
        for (int s = 0; s < 10; s++) nxt[s] = 0.0f;
        #pragma unroll
        for (int a = 0; a < 10; a++)
            #pragma unroll
            for (int q = 0; q < 10; q++)
                nxt[(a + q) % 10] = fmaf(cur[a], dd[q], nxt[(a + q) % 10]);
        #pragma unroll
        for (int s = 0; s < 10; s++) cur[s] = nxt[s];
    }
    float t10 = 0.0f;
    #pragma unroll
    for (int a = 1; a < 10; a++) t10 = fmaf(d[a], cur[10 - a], t10);
    return logf(t10);
}

__device__ float luhn_generic(const float* __restrict__ p, int n)
{
    const int LUHN[10] = {0, 5, 1, 6, 2, 7, 3, 8, 4, 9};
    const int m = n - 1;
    float cur[10];
    {
        const float* d = p + 10;
        bool perm = ((0 & 1) == (m & 1));
        #pragma unroll
        for (int j = 0; j < 10; j++) cur[j] = perm ? d[LUHN[j]] : d[j];
    }
    for (int i = 1; i < m; i++) {
        const float* d = p + (size_t)(i + 1) * 10;
        bool perm = ((i & 1) == (m & 1));
        float dd[10];
        #pragma unroll
        for (int j = 0; j < 10; j++) dd[j] = perm ? d[LUHN[j]] : d[j];
        float nxt[10];
        #pragma unroll
        for (int s = 0; s < 10; s++) nxt[s] = 0.0f;
        #pragma unroll
        for (int a = 0; a < 10; a++)
            #pragma unroll
            for (int q = 0; q < 10; q++)
                nxt[(a + q) % 10] = fmaf(cur[a], dd[q], nxt[(a + q) % 10]);
        #pragma unroll
        for (int s = 0; s < 10; s++) cur[s] = nxt[s];
    }
    float t10 = 0.0f;
    #pragma unroll
    for (int a = 1; a < 10; a++) t10 = fmaf(p[a], cur[10 - a], t10);
    return logf(t10);
}

__global__ void luhn_kernel(float* __restrict__ out, int B, int n)
{
    int b = blockIdx.x * blockDim.x + threadIdx.x;
    if (b >= B) return;
    const float* p = g_probs + (size_t)b * n * 10;
    if (n == 16) out[b] = luhn_eval<16>(p);
    else         out[b] = luhn_generic(p, n);
}

// ---------------------------------------------------------------------------
extern "C" void kernel_launch(void* const* d_in, const int* in_sizes, int n_in,
                              void* d_out, int out_size)
{
    const float* inputs = (const float*)d_in[0];
    const float* cw1    = (const float*)d_in[1];
    const float* cb1    = (const float*)d_in[2];
    const float* cw2    = (const float*)d_in[3];
    const float* cb2    = (const float*)d_in[4];
    const float* dw1    = (const float*)d_in[5];
    const float* db1    = (const float*)d_in[6];
    const float* dw2    = (const float*)d_in[7];
    const float* db2    = (const float*)d_in[8];
    const float* dw3    = (const float*)d_in[9];
    const float* db3    = (const float*)d_in[10];
    float* out = (float*)d_out;

    const int B = out_size;                      // 1024
    const int n = in_sizes[0] / (B * 784);       // 16
    const int nimg = B * n;

    const size_t smem_bytes = SMEM_FLOATS * sizeof(float);  // 229,888 B
    cudaFuncSetAttribute(cnn_kernel, cudaFuncAttributeMaxDynamicSharedMemorySize,
                         (int)smem_bytes);

    cnn_kernel<<<148, 512, smem_bytes>>>(inputs, cw1, cb1, cw2, cb2,
                                         dw1, db1, dw2, db2, dw3, db3, nimg);
    luhn_kernel<<<(B + 127) / 128, 128>>>(out, B, n);
}

// round 14
// speedup vs baseline: 1.2833x; 1.2833x over previous
#include <cuda_runtime.h>
#include <math.h>

typedef unsigned long long ull;

// ---------------------------------------------------------------------------
// packed fp32x2 helpers (Blackwell FFMA2)
// ---------------------------------------------------------------------------
#define FMA2(d, a, b, c) \
    asm("fma.rn.f32x2 %0, %1, %2, %3;" : "=l"(d) : "l"(a), "l"(b), "l"(c))

static __device__ __forceinline__ ull pack2(float lo, float hi) {
    ull r; asm("mov.b64 %0, {%1, %2};" : "=l"(r) : "f"(lo), "f"(hi)); return r;
}
static __device__ __forceinline__ float2 unpack2(ull v) {
    float2 r; asm("mov.b64 {%0, %1}, %2;" : "=f"(r.x), "=f"(r.y) : "l"(v)); return r;
}
static __device__ __forceinline__ ull lds64(const float* p) {
    return *reinterpret_cast<const ull*>(p);
}

// Scratch: per-image softmax probabilities (1024 batches * 16 digits * 10)
__device__ float g_probs[1024 * 16 * 10];

// ---------------------------------------------------------------------------
// shared memory layout (float offsets)
// ---------------------------------------------------------------------------
#define OFF_DW1T  0        // [120][260]  transposed dw1, 16B-aligned rows
#define DW1_STR   260
#define OFF_DW2T  31200    // [84][124]   transposed dw2, 16B-aligned rows
#define DW2_STR   124
#define OFF_DW3   41616    // 840
#define OFF_W1P   42456    // [25][8]  conv1 weights, 6 ch + 2 pad per tap
#define OFF_W2X   42656    // 2400 interleaved conv2 weights
#define OFF_B1    45056    // 8
#define OFF_B2    45064    // 16
#define OFF_DB1   45080    // 120
#define OFF_DB2   45200    // 88
#define OFF_DB3   45288    // 12
#define OFF_IMG   45300    // [4][784]
#define OFF_P1T   48436    // [4][6][12][24]  pooled conv1, dup pairs
#define P1_IMG_STR 1728
#define OFF_P2    55348    // [4][264]
#define P2_STR    264
#define OFF_FC1   56404    // [4][120]
#define OFF_FC2   56884    // [4][88]
#define OFF_LOG   57236    // [4][12]
#define SMEM_FLOATS 57284  // = 229,136 bytes

// barriers: ids 1/2 = full half (256), ids 5/6 = fc group (96)
#define HBAR(h) asm volatile("bar.sync %0, 256;" :: "r"((h) + 1) : "memory")
#define FBAR(h) asm volatile("bar.sync %0, 96;"  :: "r"((h) + 5) : "memory")

// ---------------------------------------------------------------------------
// conv1 (5x5->6) + relu + pool for a PAIR of images. t<144 active.
// ---------------------------------------------------------------------------
__device__ __noinline__ void do_conv1_pair(float* sm, int t, int slot0)
{
    if (t >= 144) return;
    const int im  = t / 72;
    const int r72 = t % 72;
    const int py = r72 / 6, xg = r72 % 6, x0 = 4 * xg;
    const float* ibase = sm + OFF_IMG + (slot0 + im) * 784 + 2 * py * 28 + x0;
    float* s_p1 = sm + OFF_P1T + (slot0 + im) * P1_IMG_STR;

    ull bp[3];
    #pragma unroll
    for (int cp = 0; cp < 3; cp++)
        bp[cp] = pack2(sm[OFF_B1 + 2 * cp], sm[OFF_B1 + 2 * cp + 1]);
    ull acc[2][4][3];
    #pragma unroll
    for (int dy = 0; dy < 2; dy++)
        #pragma unroll
        for (int dx = 0; dx < 4; dx++)
            #pragma unroll
            for (int cp = 0; cp < 3; cp++) acc[dy][dx][cp] = bp[cp];

    #pragma unroll
    for (int r = 0; r < 6; r++) {
        float4 v0 = *reinterpret_cast<const float4*>(ibase + r * 28);
        float4 v1 = *reinterpret_cast<const float4*>(ibase + r * 28 + 4);
        ull ap[8];
        ap[0] = pack2(v0.x, v0.x); ap[1] = pack2(v0.y, v0.y);
        ap[2] = pack2(v0.z, v0.z); ap[3] = pack2(v0.w, v0.w);
        ap[4] = pack2(v1.x, v1.x); ap[5] = pack2(v1.y, v1.y);
        ap[6] = pack2(v1.z, v1.z); ap[7] = pack2(v1.w, v1.w);
        #pragma unroll
        for (int dy = 0; dy < 2; dy++) {
            const int ky = r - dy;
            if (ky < 0 || ky > 4) continue;
            #pragma unroll
            for (int kx = 0; kx < 5; kx++) {
                const float* wp = sm + OFF_W1P + (ky * 5 + kx) * 8;
                ulonglong2 w01 = *reinterpret_cast<const ulonglong2*>(wp);
                ull w2 = lds64(wp + 4);
                #pragma unroll
                for (int dx = 0; dx < 4; dx++) {
                    FMA2(acc[dy][dx][0], ap[kx + dx], w01.x, acc[dy][dx][0]);
                    FMA2(acc[dy][dx][1], ap[kx + dx], w01.y, acc[dy][dx][1]);
                    FMA2(acc[dy][dx][2], ap[kx + dx], w2,    acc[dy][dx][2]);
                }
            }
        }
    }
    #pragma unroll
    for (int cp = 0; cp < 3; cp++) {
        #pragma unroll
        for (int dxp = 0; dxp < 2; dxp++) {
            float2 a0 = unpack2(acc[0][2 * dxp][cp]);
            float2 a1 = unpack2(acc[0][2 * dxp + 1][cp]);
            float2 b0 = unpack2(acc[1][2 * dxp][cp]);
            float2 b1 = unpack2(acc[1][2 * dxp + 1][cp]);
            float m0 = fmaxf(fmaxf(fmaxf(a0.x, a1.x), fmaxf(b0.x, b1.x)), 0.0f);
            float m1 = fmaxf(fmaxf(fmaxf(a0.y, a1.y), fmaxf(b0.y, b1.y)), 0.0f);
            const int px = 2 * xg + dxp;
            *reinterpret_cast<ull*>(s_p1 + ((2 * cp)     * 12 + py) * 24 + 2 * px) = pack2(m0, m0);
            *reinterpret_cast<ull*>(s_p1 + ((2 * cp + 1) * 12 + py) * 24 + 2 * px) = pack2(m1, m1);
        }
    }
}

// ---------------------------------------------------------------------------
// conv2 (5x5x6->16) + relu + pool on ALL 256 threads of a half.
// thread t = (im, py 0..3, xg 0..3, cg 0..7): conv rows 2py..2py+1, conv cols
// 2xg..2xg+1, channels 2cg..2cg+1. Complete 2x2 pooled cell per thread —
// no cross-thread exchange, no state across barriers.
// Warp dedup: w addresses vary only with cg (8 x 16B = 1 wf); act addresses
// vary only with xg (4 unique = 1 wf).
// ---------------------------------------------------------------------------
__device__ __noinline__ void do_conv2_all(float* sm, int t, int slot0)
{
    const int im = t >> 7;
    const int py = (t >> 5) & 3;
    const int xg = (t >> 3) & 3;
    const int cg = t & 7;
    const float* pbase = sm + OFF_P1T + (slot0 + im) * P1_IMG_STR;
    const float* wbase = sm + OFF_W2X + cg * 4;

    ull bp = lds64(sm + OFF_B2 + 2 * cg);
    ull acc[2][2];
    acc[0][0] = bp; acc[0][1] = bp; acc[1][0] = bp; acc[1][1] = bp;

    #pragma unroll
    for (int r = 0; r < 6; r++) {
        const int iy = 2 * py + r;
        #pragma unroll
        for (int ip = 0; ip < 3; ip++) {
            const float* r0 = pbase + ((2 * ip) * 12 + iy) * 24 + 4 * xg;
            const float* r1 = r0 + 288;
            ulonglong2 a0a = *reinterpret_cast<const ulonglong2*>(r0);
            ulonglong2 a0b = *reinterpret_cast<const ulonglong2*>(r0 + 4);
            ulonglong2 a0c = *reinterpret_cast<const ulonglong2*>(r0 + 8);
            ulonglong2 a1a = *reinterpret_cast<const ulonglong2*>(r1);
            ulonglong2 a1b = *reinterpret_cast<const ulonglong2*>(r1 + 4);
            ulonglong2 a1c = *reinterpret_cast<const ulonglong2*>(r1 + 8);
            ull ap0[6] = {a0a.x, a0a.y, a0b.x, a0b.y, a0c.x, a0c.y};
            ull ap1[6] = {a1a.x, a1a.y, a1b.x, a1b.y, a1c.x, a1c.y};
            #pragma unroll
            for (int dy = 0; dy < 2; dy++) {
                const int ky = r - dy;
                if (ky < 0 || ky > 4) continue;
                #pragma unroll
                for (int kx = 0; kx < 5; kx++) {
                    ulonglong2 w = *reinterpret_cast<const ulonglong2*>(
                        wbase + ((ky * 5 + kx) * 3 + ip) * 32);
                    FMA2(acc[dy][0], ap0[kx],     w.x, acc[dy][0]);
                    FMA2(acc[dy][0], ap1[kx],     w.y, acc[dy][0]);
                    FMA2(acc[dy][1], ap0[kx + 1], w.x, acc[dy][1]);
                    FMA2(acc[dy][1], ap1[kx + 1], w.y, acc[dy][1]);
                }
            }
        }
    }
    float2 a0 = unpack2(acc[0][0]);
    float2 a1 = unpack2(acc[0][1]);
    float2 b0 = unpack2(acc[1][0]);
    float2 b1 = unpack2(acc[1][1]);
    float m0 = fmaxf(fmaxf(fmaxf(a0.x, a1.x), fmaxf(b0.x, b1.x)), 0.0f);
    float m1 = fmaxf(fmaxf(fmaxf(a0.y, a1.y), fmaxf(b0.y, b1.y)), 0.0f);
    float* s_p2 = sm + OFF_P2 + (slot0 + im) * P2_STR;
    *reinterpret_cast<ull*>(s_p2 + (py * 4 + xg) * 16 + 2 * cg) = pack2(m0, m1);
}

// ---------------------------------------------------------------------------
// fc chain on 96 threads (tF = 0..95).
// ---------------------------------------------------------------------------
static __device__ __forceinline__ void do_fc1_96(float* sm, int tF, int slot0)
{
    for (int u = tF; u < 240; u += 96) {
        const int j = u >> 1, im = u & 1;
        const float* act = sm + OFF_P2 + (slot0 + im) * P2_STR;
        const float* wr  = sm + OFF_DW1T + j * DW1_STR;
        ull acc0 = pack2(0.0f, 0.0f), acc1 = pack2(0.0f, 0.0f);
        #pragma unroll 8
        for (int k = 0; k < 256; k += 4) {
            ulonglong2 av = *reinterpret_cast<const ulonglong2*>(act + k);
            ulonglong2 wv = *reinterpret_cast<const ulonglong2*>(wr + k);
            FMA2(acc0, av.x, wv.x, acc0);
            FMA2(acc1, av.y, wv.y, acc1);
        }
        float2 s0 = unpack2(acc0), s1 = unpack2(acc1);
        float v = s0.x + s0.y + s1.x + s1.y + sm[OFF_DB1 + j];
        sm[OFF_FC1 + (slot0 + im) * 120 + j] = fmaxf(v, 0.0f);
    }
}

static __device__ __forceinline__ void do_fc2_96(float* sm, int tF, int slot0)
{
    for (int u = tF; u < 168; u += 96) {
        const int j = u >> 1, im = u & 1;
        const float* act = sm + OFF_FC1 + (slot0 + im) * 120;
        const float* wr  = sm + OFF_DW2T + j * DW2_STR;
        ull acc0 = pack2(0.0f, 0.0f), acc1 = pack2(0.0f, 0.0f);
        #pragma unroll 6
        for (int k = 0; k < 120; k += 4) {
            ulonglong2 av = *reinterpret_cast<const ulonglong2*>(act + k);
            ulonglong2 wv = *reinterpret_cast<const ulonglong2*>(wr + k);
            FMA2(acc0, av.x, wv.x, acc0);
            FMA2(acc1, av.y, wv.y, acc1);
        }
        float2 s0 = unpack2(acc0), s1 = unpack2(acc1);
        float v = s0.x + s0.y + s1.x + s1.y + sm[OFF_DB2 + j];
        sm[OFF_FC2 + (slot0 + im) * 88 + j] = fmaxf(v, 0.0f);
    }
}

// fc3 (20 units) + softmax (2 units), inside one warp (tF 0..31).
static __device__ __forceinline__ void do_fc3_softmax_96(float* sm, int tF, int slot0,
                                                         int img0, int nimg)
{
    if (tF >= 32) return;
    if (tF < 20) {
        const int j = tF >> 1, im = tF & 1;
        const float* act = sm + OFF_FC2 + (slot0 + im) * 88;
        float acc = sm[OFF_DB3 + j];
        #pragma unroll 4
        for (int k = 0; k < 84; k++)
            acc = fmaf(act[k], sm[OFF_DW3 + k * 10 + j], acc);
        sm[OFF_LOG + (slot0 + im) * 12 + j] = acc;
    }
    __syncwarp();
    if (tF < 2) {
        const int img = img0 + tF;
        if (img < nimg) {
            const float* lg = sm + OFF_LOG + (slot0 + tF) * 12;
            float mx = lg[0];
            #pragma unroll
            for (int j = 1; j < 10; j++) mx = fmaxf(mx, lg[j]);
            float e[10], s = 0.0f;
            #pragma unroll
            for (int j = 0; j < 10; j++) { e[j] = __expf(lg[j] - mx); s += e[j]; }
            float inv = 1.0f / s;
            float* po = g_probs + (size_t)img * 10;
            #pragma unroll
            for (int j = 0; j < 10; j++) po[j] = e[j] * inv;
        }
    }
}

// prefetch by 16 threads (tP = 0..15): copy this half's next 2 images.
static __device__ __forceinline__ void do_prefetch16(float* sm, int tP, int slot0,
                                                     const float* inputs,
                                                     int nb, int nimg)
{
    if (nb + slot0 < nimg) {
        const float4* iv = reinterpret_cast<const float4*>(inputs + (size_t)(nb + slot0) * 784);
        float4* ov = reinterpret_cast<float4*>(sm + OFF_IMG + slot0 * 784);
        for (int i = tP; i < 196; i += 16) ov[i] = iv[i];
    }
    if (nb + slot0 + 1 < nimg) {
        const float4* iv = reinterpret_cast<const float4*>(inputs + (size_t)(nb + slot0 + 1) * 784);
        float4* ov = reinterpret_cast<float4*>(sm + OFF_IMG + (slot0 + 1) * 784);
        for (int i = tP; i < 196; i += 16) ov[i] = iv[i];
    }
}

// ---------------------------------------------------------------------------
// Kernel 1: persistent fused LeNet. 148 CTAs x 512 threads; two independent
// 256-thread halves, each a 2-stage software pipeline over pairs of images:
//   P1: conv2(cur) on ALL 256 threads (short pole, no exchange)
//   P2: conv1(next) [t<144] || prefetch(next) [t 144-159] || fc chain(cur) [t>=160]
// ---------------------------------------------------------------------------
__global__ void __launch_bounds__(512, 1) cnn_kernel(
    const float* __restrict__ inputs,
    const float* __restrict__ cw1, const float* __restrict__ cb1,
    const float* __restrict__ cw2, const float* __restrict__ cb2,
    const float* __restrict__ dw1, const float* __restrict__ db1,
    const float* __restrict__ dw2, const float* __restrict__ db2,
    const float* __restrict__ dw3, const float* __restrict__ db3,
    int nimg)
{
    extern __shared__ float sm[];
    const int tid = threadIdx.x;

    // ---- one-time weight staging ----
    for (int idx = tid; idx < 256 * 120; idx += 512) {
        int k = idx / 120, j = idx % 120;
        sm[OFF_DW1T + j * DW1_STR + k] = dw1[idx];
    }
    for (int idx = tid; idx < 120 * 84; idx += 512) {
        int k = idx / 84, j = idx % 84;
        sm[OFF_DW2T + j * DW2_STR + k] = dw2[idx];
    }
    for (int idx = tid; idx < 840; idx += 512) sm[OFF_DW3 + idx] = dw3[idx];
    for (int idx = tid; idx < 150; idx += 512) {
        int pk = idx / 6, c = idx % 6;
        sm[OFF_W1P + pk * 8 + c] = cw1[idx];
    }
    for (int idx = tid; idx < 2400; idx += 512) {
        int p = idx >> 4, ch = idx & 15;
        int pk = p / 6, i = p % 6;
        sm[OFF_W2X + (pk * 3 + (i >> 1)) * 32 + (ch >> 1) * 4 + (i & 1) * 2 + (ch & 1)]
            = cw2[idx];
    }
    if (tid < 6)   sm[OFF_B1  + tid] = cb1[tid];
    if (tid < 16)  sm[OFF_B2  + tid] = cb2[tid];
    if (tid < 120) sm[OFF_DB1 + tid] = db1[tid];
    if (tid < 84)  sm[OFF_DB2 + tid] = db2[tid];
    if (tid < 10)  sm[OFF_DB3 + tid] = db3[tid];

    // ---- prologue: load first batch of 4 images (guarded per image) ----
    {
        const int b0 = blockIdx.x * 4;
        #pragma unroll
        for (int k = 0; k < 4; k++) {
            if (b0 + k < nimg) {
                const float4* iv = reinterpret_cast<const float4*>(inputs + (size_t)(b0 + k) * 784);
                float4* ov = reinterpret_cast<float4*>(sm + OFF_IMG + k * 784);
                for (int i = tid; i < 196; i += 512) ov[i] = iv[i];
            }
        }
    }
    __syncthreads();

    const int h     = tid >> 8;      // half 0/1
    const int t     = tid & 255;     // thread within half
    const int slot0 = h * 2;
    const int qstep = gridDim.x * 4;

    // ---- pipeline prologue: conv1 on the first pair ----
    do_conv1_pair(sm, t, slot0);
    HBAR(h);

    for (int base = blockIdx.x * 4; base < nimg; base += qstep) {
        // P1: conv2(cur) on all 256 threads
        do_conv2_all(sm, t, slot0);
        HBAR(h);

        // P2: conv1(next) || prefetch(next) || fc chain(cur)
        if (t < 144) {
            do_conv1_pair(sm, t, slot0);     // harmless on stale data past end
        } else if (t < 160) {
            do_prefetch16(sm, t - 144, slot0, inputs, base + qstep, nimg);
        } else {
            const int tF = t - 160;
            do_fc1_96(sm, tF, slot0);
            FBAR(h);
            do_fc2_96(sm, tF, slot0);
            FBAR(h);
            do_fc3_softmax_96(sm, tF, slot0, base + slot0, nimg);
        }
        HBAR(h);
    }
}

// ---------------------------------------------------------------------------
// Kernel 2: Luhn DP (register-resident, high-MLP loads).
// ---------------------------------------------------------------------------
template <int N>
__device__ __forceinline__ float luhn_eval(const float* __restrict__ p)
{
    const int LUHN[10] = {0, 5, 1, 6, 2, 7, 3, 8, 4, 9};
    float4 v[(N * 10) / 4];
    const float4* pv = reinterpret_cast<const float4*>(p);
    #pragma unroll
    for (int i = 0; i < (N * 10) / 4; i++) v[i] = pv[i];
    float d[N * 10];
    #pragma unroll
    for (int i = 0; i < (N * 10) / 4; i++) {
        d[4 * i] = v[i].x; d[4 * i + 1] = v[i].y;
        d[4 * i + 2] = v[i].z; d[4 * i + 3] = v[i].w;
    }
    const int m = N - 1;
    float cur[10];
    #pragma unroll
    for (int j = 0; j < 10; j++)
        cur[j] = ((0 % 2) == (m % 2)) ? d[10 + LUHN[j]] : d[10 + j];
    #pragma unroll
    for (int i = 1; i < m; i++) {
        float dd[10];
        #pragma unroll
        for (int j = 0; j < 10; j++)
            dd[j] = ((i % 2) == (m % 2)) ? d[(i + 1) * 10 + LUHN[j]] : d[(i + 1) * 10 + j];
        float nxt[10];
        #pragma unroll
        for (int s = 0; s < 10; s++) nxt[s] = 0.0f;
        #pragma unroll
        for (int a = 0; a < 10; a++)
            #pragma unroll
            for (int q = 0; q < 10; q++)
                nxt[(a + q) % 10] = fmaf(cur[a], dd[q], nxt[(a + q) % 10]);
        #pragma unroll
        for (int s = 0; s < 10; s++) cur[s] = nxt[s];
    }
    float t10 = 0.0f;
    #pragma unroll
    for (int a = 1; a < 10; a++) t10 = fmaf(d[a], cur[10 - a], t10);
    return logf(t10);
}

__device__ float luhn_generic(const float* __restrict__ p, int n)
{
    const int LUHN[10] = {0, 5, 1, 6, 2, 7, 3, 8, 4, 9};
    const int m = n - 1;
    float cur[10];
    {
        const float* d = p + 10;
        bool perm = ((0 & 1) == (m & 1));
        #pragma unroll
        for (int j = 0; j < 10; j++) cur[j] = perm ? d[LUHN[j]] : d[j];
    }
    for (int i = 1; i < m; i++) {
        const float* d = p + (size_t)(i + 1) * 10;
        bool perm = ((i & 1) == (m & 1));
        float dd[10];
        #pragma unroll
        for (int j = 0; j < 10; j++) dd[j] = perm ? d[LUHN[j]] : d[j];
        float nxt[10];
        #pragma unroll
        for (int s = 0; s < 10; s++) nxt[s] = 0.0f;
        #pragma unroll
        for (int a = 0; a < 10; a++)
            #pragma unroll
            for (int q = 0; q < 10; q++)
                nxt[(a + q) % 10] = fmaf(cur[a], dd[q], nxt[(a + q) % 10]);
        #pragma unroll
        for (int s = 0; s < 10; s++) cur[s] = nxt[s];
    }
    float t10 = 0.0f;
    #pragma unroll
    for (int a = 1; a < 10; a++) t10 = fmaf(p[a], cur[10 - a], t10);
    return logf(t10);
}

__global__ void luhn_kernel(float* __restrict__ out, int B, int n)
{
    int b = blockIdx.x * blockDim.x + threadIdx.x;
    if (b >= B) return;
    const float* p = g_probs + (size_t)b * n * 10;
    if (n == 16) out[b] = luhn_eval<16>(p);
    else         out[b] = luhn_generic(p, n);
}

// ---------------------------------------------------------------------------
extern "C" void kernel_launch(void* const* d_in, const int* in_sizes, int n_in,
                              void* d_out, int out_size)
{
    const float* inputs = (const float*)d_in[0];
    const float* cw1    = (const float*)d_in[1];
    const float* cb1    = (const float*)d_in[2];
    const float* cw2    = (const float*)d_in[3];
    const float* cb2    = (const float*)d_in[4];
    const float* dw1    = (const float*)d_in[5];
    const float* db1    = (const float*)d_in[6];
    const float* dw2    = (const float*)d_in[7];
    const float* db2    = (const float*)d_in[8];
    const float* dw3    = (const float*)d_in[9];
    const float* db3    = (const float*)d_in[10];
    float* out = (float*)d_out;

    const int B = out_size;                      // 1024
    const int n = in_sizes[0] / (B * 784);       // 16
    const int nimg = B * n;

    const size_t smem_bytes = SMEM_FLOATS * sizeof(float);  // 229,136 B
    cudaFuncSetAttribute(cnn_kernel, cudaFuncAttributeMaxDynamicSharedMemorySize,
                         (int)smem_bytes);

    cnn_kernel<<<148, 512, smem_bytes>>>(inputs, cw1, cb1, cw2, cb2,
                                         dw1, db1, dw2, db2, dw3, db3, nimg);
    luhn_kernel<<<(B + 127) / 128, 128>>>(out, B, n);
}